// round 16
// baseline (speedup 1.0000x reference)
#include <cuda_runtime.h>
#include <math.h>

#define NMODES 64
#define LSEQ   262144
#define NSEGS  8192              /* segments of 32 samples */
#define SCAN_T 1024
#define CPT    8                 /* segs per scan thread */
#define LEVELS 10                /* log2(SCAN_T) */

#define KA_GRID 1024
#define KA_THR  128
#define KC_CHUNK 8
#define KC_GRID (NSEGS/KC_CHUNK) /* 1024 */
#define KC_THR  256
#define RSTR    12               /* sR row stride, float4-aligned */

// ---------------- scratch (static device globals; no allocation) ----------------
__device__ float g_Mt[160 * 32];     // [K][t] K<32: Toeplitz W (D folded); K>=32: carry proj
__device__ float g_Pp[128 * NSEGS];  // planar P: rows 0..63 re, 64..127 im
__device__ float g_Xc[128 * NSEGS];  // planar carries, same layout

// ---------------- z^e, double phase (large e) ----------------
static __device__ __forceinline__ float2 cexp_pow_d(double dr, double di, double e) {
    float m = expf((float)(e * dr));
    double t = e * di;
    double q = rint(t * 0.15915494309189533576888376337251);
    double r = fma(q, -6.283185307179586476925286766559, t);
    float s, c;
    sincosf((float)r, &s, &c);
    return make_float2(m * c, m * s);
}
// ---------------- z^e, fp32 phase (e <= 33; verified R13-R15) ----------------
static __device__ __forceinline__ float2 cexp_pow_f(float dr, float di, float e) {
    float m = expf(e * dr);
    float t = e * di;
    float q = rintf(t * 0.15915494309189533576888376337251f);
    float r = fmaf(q, -6.283185307179586476925286766559f, t);
    float s, c;
    sincosf(r, &s, &c);
    return make_float2(m * c, m * s);
}
static __device__ __forceinline__ float2 cmulf(float2 a, float2 b) {
    return make_float2(fmaf(a.x, b.x, -(a.y * b.y)), fmaf(a.x, b.y, a.y * b.x));
}

// ---------------- kA: P[128][8192] = V @ U, vv via 4 parallel chains ----------------
// grid = 1024 blocks x 128 thr; block covers 8 segs (256 samples).
// Thread = one P row (mode m = t&63, part = t>>6). Inner loop: 2 LDS.128 + 8 FFMA.
__global__ void __launch_bounds__(KA_THR) kA_pgemm(const float* __restrict__ u,
                                                   const float* __restrict__ A_re,
                                                   const float* __restrict__ A_im,
                                                   const float* __restrict__ log_step) {
    __shared__ float sU[32 * 8];     // [k][seg] 1 KB
    int t = threadIdx.x, c = blockIdx.x;
    int m = t & 63, part = t >> 6;

    const float* ub = u + c * 256;
    for (int i = t; i < 256; i += KA_THR)
        sU[(i & 31) * 8 + (i >> 5)] = ub[i];

    float dtf = expf(log_step[0]);
    float fdr = dtf * A_re[m], fdi = dtf * A_im[m];
    float2 z  = cexp_pow_f(fdr, fdi, 1.0f);
    float2 z2 = cmulf(z, z);
    float2 z3 = cmulf(z2, z);
    float2 z4 = cmulf(z2, z2);

    // vv[e] = part ? Im(z^e) : Re(z^e) — 4 independent stride-4 chains
    float vv[32];
    {
        float2 c0 = make_float2(1.f, 0.f), c1 = z, c2 = z2, c3 = z3;
#pragma unroll
        for (int e4 = 0; e4 < 8; e4++) {
            vv[4 * e4 + 0] = part ? c0.y : c0.x;
            vv[4 * e4 + 1] = part ? c1.y : c1.x;
            vv[4 * e4 + 2] = part ? c2.y : c2.x;
            vv[4 * e4 + 3] = part ? c3.y : c3.x;
            c0 = cmulf(c0, z4); c1 = cmulf(c1, z4);
            c2 = cmulf(c2, z4); c3 = cmulf(c3, z4);
        }
    }
    __syncthreads();

    float a0 = 0.f, a1 = 0.f, a2 = 0.f, a3 = 0.f;
    float a4 = 0.f, a5 = 0.f, a6 = 0.f, a7 = 0.f;
#pragma unroll
    for (int e = 0; e < 32; e++) {
        const int k = 31 - e;                       // compile-time
        float  v  = vv[e];
        float4 u0 = *(const float4*)&sU[k * 8];     // warp-uniform broadcast
        float4 u1 = *(const float4*)&sU[k * 8 + 4];
        a0 = fmaf(v, u0.x, a0); a1 = fmaf(v, u0.y, a1);
        a2 = fmaf(v, u0.z, a2); a3 = fmaf(v, u0.w, a3);
        a4 = fmaf(v, u1.x, a4); a5 = fmaf(v, u1.y, a5);
        a6 = fmaf(v, u1.z, a6); a7 = fmaf(v, u1.w, a7);
    }
    float4* pr = (float4*)&g_Pp[t * NSEGS + c * 8];
    pr[0] = make_float4(a0, a1, a2, a3);
    pr[1] = make_float4(a4, a5, a6, a7);
}

// ---------------- kB: per-mode fp32 scan; block 0 also builds g_Mt ----------------
#define BSTEP(Er, Ei, pr, pi)                          \
    do {                                               \
        float _tr = fmaf(-a.y, (Ei), (pr));            \
        float _ti = fmaf( a.y, (Er), (pi));            \
        (Er) = fmaf(a.x, (Er), _tr);                   \
        (Ei) = fmaf(a.x, (Ei), _ti);                   \
    } while (0)

__global__ void __launch_bounds__(SCAN_T) kB_scan(const float* __restrict__ A_re,
                                                  const float* __restrict__ A_im,
                                                  const float* __restrict__ C,
                                                  const float* __restrict__ D,
                                                  const float* __restrict__ log_step) {
    __shared__ float smr[SCAN_T];
    __shared__ float smi[SCAN_T];
    __shared__ float sW[32 * 64];          // block 0 Mt build
    __shared__ float sWl[32];
    __shared__ float2 s_mul[LEVELS + 1];   // [0..9] KS multipliers, [10] z^32
    int n = blockIdx.x, t = threadIdx.x;

    // ---- block 0: build Mt (Toeplitz + carry projection), fp32 path ----
    if (n == 0 && t < 256) {
        int m = t & 63, g = t >> 6;        // 4 groups x 8 exponents
        float dtf = expf(log_step[0]);
        float fdr = dtf * A_re[m], fdi = dtf * A_im[m];
        float2 z = cexp_pow_f(fdr, fdi, 1.0f);
        float ar = A_re[m], ai = A_im[m];
        float ctr = C[2 * m], cti = C[2 * m + 1];
        float wr = z.x - 1.f, wi = z.y;
        float den = ar * ar + ai * ai;
        float qr = (wr * ar + wi * ai) / den;
        float qi = (wi * ar - wr * ai) / den;
        float cfr = ctr * qr - cti * qi;
        float cfi = ctr * qi + cti * qr;
#pragma unroll
        for (int j = 0; j < 8; j++) {
            int e = 8 * g + j;
            float2 we = cexp_pow_f(fdr, fdi, (float)e);
            sW[e * 64 + m] = cfr * we.x - cfi * we.y;             // Re(c z^e)
            float2 w1 = cexp_pow_f(fdr, fdi, (float)(e + 1));
            g_Mt[(32 + m) * 32 + e] = cfr * w1.x - cfi * w1.y;    // Re(c z^{t+1})
            g_Mt[(96 + m) * 32 + e] = -(cfr * w1.y + cfi * w1.x); // -Im(c z^{t+1})
        }
    }
    if (t <= LEVELS) {                     // per-block scan constants (double phase)
        double dt = exp((double)log_step[0]);
        double dr = dt * (double)A_re[n], di = dt * (double)A_im[n];
        double e = (t == LEVELS) ? 32.0 : 256.0 * (double)(1 << t);
        s_mul[t] = cexp_pow_d(dr, di, e);
    }
    __syncthreads();
    if (n == 0 && t < 32) {
        float s = 0.f;
        for (int mm = 0; mm < 64; mm++) s += sW[t * 64 + mm];
        sWl[t] = s;                        // W[l] = Re sum_n c_n z_n^l
    }
    __syncthreads();
    if (n == 0 && t < 1024) {
        int k = t >> 5, tt = t & 31;
        float v = (tt >= k) ? sWl[tt - k] : 0.f;
        if (tt == k) v += D[0];            // fold D*u into Toeplitz diagonal
        g_Mt[k * 32 + tt] = v;
    }

    // ---- scan (verified body) ----
    float2 a = s_mul[LEVELS];
    const float* pre = &g_Pp[n * NSEGS];
    const float* pim = &g_Pp[(64 + n) * NSEGS];
    int s0 = t * CPT;

    float Br = 0.f, Bi = 0.f;
#pragma unroll
    for (int j = 0; j < CPT; j += 4) {
        float4 r4 = *(const float4*)&pre[s0 + j];
        float4 i4 = *(const float4*)&pim[s0 + j];
        BSTEP(Br, Bi, r4.x, i4.x);
        BSTEP(Br, Bi, r4.y, i4.y);
        BSTEP(Br, Bi, r4.z, i4.z);
        BSTEP(Br, Bi, r4.w, i4.w);
    }
    smr[t] = Br; smi[t] = Bi;
#pragma unroll
    for (int k = 0; k < LEVELS; k++) {
        int off = 1 << k;
        float2 mm = s_mul[k];
        __syncthreads();
        float lr = 0.f, li = 0.f;
        if (t >= off) { lr = smr[t - off]; li = smi[t - off]; }
        __syncthreads();
        if (t >= off) {
            float nr = fmaf(mm.x, lr, fmaf(-mm.y, li, Br));
            float ni = fmaf(mm.x, li, fmaf( mm.y, lr, Bi));
            Br = nr; Bi = ni;
            smr[t] = Br; smi[t] = Bi;
        }
    }
    __syncthreads();
    float Er = 0.f, Ei = 0.f;
    if (t > 0) { Er = smr[t - 1]; Ei = smi[t - 1]; }
    float* xre = &g_Xc[n * NSEGS];
    float* xim = &g_Xc[(64 + n) * NSEGS];
#pragma unroll
    for (int j = 0; j < CPT; j += 4) {
        float4 r4 = *(const float4*)&pre[s0 + j];
        float4 i4 = *(const float4*)&pim[s0 + j];
        float4 orv, oiv;
        orv.x = Er; oiv.x = Ei; BSTEP(Er, Ei, r4.x, i4.x);
        orv.y = Er; oiv.y = Ei; BSTEP(Er, Ei, r4.y, i4.y);
        orv.z = Er; oiv.z = Ei; BSTEP(Er, Ei, r4.z, i4.z);
        orv.w = Er; oiv.w = Ei; BSTEP(Er, Ei, r4.w, i4.w);
        *(float4*)&xre[s0 + j] = orv;
        *(float4*)&xim[s0 + j] = oiv;
    }
}

// ---------------- kC: Y = Mt^T @ [U;Xc], 8-warp K-split, 8 acc/thread ----------------
// grid = 1024 blocks (8 segs each) x 256 thr. Warp w: k in [20w,20w+20); row = lane.
// smem 28.2 KB -> 8 blocks/SM; sRed aliases sMt after compute.
__global__ void __launch_bounds__(KC_THR) kC_ygemm(const float* __restrict__ u,
                                                   float* __restrict__ y) {
    __shared__ float sMt[160 * 32];      // 20 KB; reused as sRed[8*256] after compute
    __shared__ float sR[160 * RSTR];     // 7.5 KB
    int t = threadIdx.x, b = blockIdx.x;
    int ss = b * KC_CHUNK;

    {   // stage Mt, coalesced float4
        const float4* src = (const float4*)g_Mt;
        float4* dst = (float4*)sMt;
        for (int i = t; i < 1280; i += KC_THR) dst[i] = src[i];
    }
    // R rows 0..31 = U^T: 8 segs x 32 k
    {
        int seg = t >> 5, k = t & 31;
        sR[k * RSTR + seg] = u[ss * 32 + t];
    }
    // R rows 32..159 = Xc rows 0..127, float2 both sides
    {
        int rr = t >> 1, c2 = t & 1;
        float2 v = *(const float2*)&g_Xc[rr * NSEGS + ss + 4 * c2];
        *(float2*)&sR[(32 + rr) * RSTR + 4 * c2] = v;
        float2 v2 = *(const float2*)&g_Xc[rr * NSEGS + ss + 4 * c2 + 2];
        *(float2*)&sR[(32 + rr) * RSTR + 4 * c2 + 2] = v2;
    }
    __syncthreads();

    int lane = t & 31, w = t >> 5;       // 8 warps
    int kbase = w * 20;
    float acc[8];
#pragma unroll
    for (int j = 0; j < 8; j++) acc[j] = 0.f;
#pragma unroll 5
    for (int kk = 0; kk < 20; kk++) {
        int k = kbase + kk;
        float  mv = sMt[k * 32 + lane];             // conflict-free LDS.32
        float4 r0 = *(const float4*)&sR[k * RSTR];  // broadcasts
        float4 r1 = *(const float4*)&sR[k * RSTR + 4];
        acc[0] = fmaf(mv, r0.x, acc[0]); acc[1] = fmaf(mv, r0.y, acc[1]);
        acc[2] = fmaf(mv, r0.z, acc[2]); acc[3] = fmaf(mv, r0.w, acc[3]);
        acc[4] = fmaf(mv, r1.x, acc[4]); acc[5] = fmaf(mv, r1.y, acc[5]);
        acc[6] = fmaf(mv, r1.z, acc[6]); acc[7] = fmaf(mv, r1.w, acc[7]);
    }
    __syncthreads();                     // everyone done READING sMt
    float* sRed = sMt;                   // alias: 8 warps * 256 floats
#pragma unroll
    for (int j = 0; j < 8; j++) sRed[w * 256 + j * 32 + lane] = acc[j];
    __syncthreads();

    {   // fixed-order 8-way sum, coalesced write
        float s = ((sRed[t]        + sRed[256 + t])  + (sRed[512 + t]  + sRed[768 + t]))
                + ((sRed[1024 + t] + sRed[1280 + t]) + (sRed[1536 + t] + sRed[1792 + t]));
        y[ss * 32 + t] = s;
    }
}

// ---------------- host: 3 kernel nodes ----------------
extern "C" void kernel_launch(void* const* d_in, const int* in_sizes, int n_in,
                              void* d_out, int out_size) {
    const float* u = 0; const float* A_re = 0; const float* A_im = 0;
    const float* C = 0; const float* D = 0; const float* log_step = 0;
    for (int i = 0; i < n_in; i++) {
        int sz = in_sizes[i];
        const float* p = (const float*)d_in[i];
        if (sz == LSEQ)            { if (!u) u = p; }
        else if (sz == 2 * NMODES) { if (!C) C = p; }
        else if (sz == NMODES)     { if (!A_re) A_re = p; else A_im = p; }
        else if (sz == 1)          { if (!D) D = p; else log_step = p; }
    }
    float* y = (float*)d_out;

    kA_pgemm<<<KA_GRID, KA_THR>>>(u, A_re, A_im, log_step);
    kB_scan<<<NMODES, SCAN_T>>>(A_re, A_im, C, D, log_step);
    kC_ygemm<<<KC_GRID, KC_THR>>>(u, y);
}